// round 1
// baseline (speedup 1.0000x reference)
#include <cuda_runtime.h>
#include <cuda_bf16.h>
#include <math.h>

// Problem constants
#define DIMN     5120
#define NHEADS   40
#define HDIM     128
#define BATCH    2
#define SEQ      1024
#define TOKENS   (BATCH * SEQ)        // 2048
#define QKV_COLS (3 * DIMN)           // 15360
#define EPSV     1e-6f
#define SCALEV   0.08838834764831845f // 128^-0.5

// Scratch (no allocations allowed)
__device__ float g_qkv[TOKENS * QKV_COLS];   // 2048 x 15360
__device__ float g_attn[TOKENS * DIMN];      // 2048 x 5120

// ---------------------------------------------------------------------------
// Generic SGEMM with bias: C[M,N] = A[M,K] @ B[K,N] + bias[N]
// BM=BN=128, BK=16, 256 threads, 8x8 per thread. M%128==0, N%128==0, K%16==0.
// ---------------------------------------------------------------------------
__global__ __launch_bounds__(256) void sgemm_bias(
    const float* __restrict__ A, const float* __restrict__ B,
    const float* __restrict__ bias, float* __restrict__ C,
    int M, int N, int K)
{
    __shared__ float As[16][132];   // transposed A tile, padded
    __shared__ float Bs[16][132];

    const int tid = threadIdx.x;
    const int tx  = tid & 15;       // 0..15 -> output cols (tx*8)
    const int ty  = tid >> 4;       // 0..15 -> output rows (ty*8)
    const int m0  = blockIdx.y * 128;
    const int n0  = blockIdx.x * 128;

    float acc[8][8];
#pragma unroll
    for (int i = 0; i < 8; ++i)
#pragma unroll
        for (int j = 0; j < 8; ++j) acc[i][j] = 0.0f;

    for (int k0 = 0; k0 < K; k0 += 16) {
        __syncthreads();
#pragma unroll
        for (int u = 0; u < 2; ++u) {
            const int id = tid * 2 + u;
            // A tile: 128 rows x 16 cols = 512 float4 (4 per row)
            const int ar  = id >> 2;
            const int ac4 = (id & 3) * 4;
            float4 av = *(const float4*)(A + (size_t)(m0 + ar) * K + k0 + ac4);
            As[ac4 + 0][ar] = av.x;
            As[ac4 + 1][ar] = av.y;
            As[ac4 + 2][ar] = av.z;
            As[ac4 + 3][ar] = av.w;
            // B tile: 16 rows x 128 cols = 512 float4 (32 per row)
            const int br  = id >> 5;
            const int bc4 = (id & 31) * 4;
            float4 bv = *(const float4*)(B + (size_t)(k0 + br) * N + n0 + bc4);
            *(float4*)&Bs[br][bc4] = bv;
        }
        __syncthreads();

#pragma unroll
        for (int kk = 0; kk < 16; ++kk) {
            float4 a0 = *(const float4*)&As[kk][ty * 8];
            float4 a1 = *(const float4*)&As[kk][ty * 8 + 4];
            float4 b0 = *(const float4*)&Bs[kk][tx * 8];
            float4 b1 = *(const float4*)&Bs[kk][tx * 8 + 4];
            float ar[8] = {a0.x, a0.y, a0.z, a0.w, a1.x, a1.y, a1.z, a1.w};
            float br[8] = {b0.x, b0.y, b0.z, b0.w, b1.x, b1.y, b1.z, b1.w};
#pragma unroll
            for (int i = 0; i < 8; ++i)
#pragma unroll
                for (int j = 0; j < 8; ++j)
                    acc[i][j] = fmaf(ar[i], br[j], acc[i][j]);
        }
    }

    // Epilogue: add bias, store
#pragma unroll
    for (int i = 0; i < 8; ++i) {
        const int row = m0 + ty * 8 + i;
        float* dst = C + (size_t)row * N + n0 + tx * 8;
        const float* bp = bias + n0 + tx * 8;
        float4 v0, v1;
        v0.x = acc[i][0] + bp[0]; v0.y = acc[i][1] + bp[1];
        v0.z = acc[i][2] + bp[2]; v0.w = acc[i][3] + bp[3];
        v1.x = acc[i][4] + bp[4]; v1.y = acc[i][5] + bp[5];
        v1.z = acc[i][6] + bp[6]; v1.w = acc[i][7] + bp[7];
        *(float4*)(dst)     = v0;
        *(float4*)(dst + 4) = v1;
    }
}

// ---------------------------------------------------------------------------
// Fused RMSNorm (over full DIM for q and k) + rotary embedding, in place.
// One block per token, 256 threads.
// ---------------------------------------------------------------------------
__global__ __launch_bounds__(256) void rms_rope(
    float* __restrict__ qkv,
    const float* __restrict__ gq, const float* __restrict__ gk,
    const float* __restrict__ fcos, const float* __restrict__ fsin)
{
    const int t   = blockIdx.x;          // token 0..2047
    const int l   = t & (SEQ - 1);       // position in sequence
    const int tid = threadIdx.x;

    float* qrow = qkv + (size_t)t * QKV_COLS;
    float* krow = qrow + DIMN;

    // sum of squares for q and k
    float sq = 0.0f, sk = 0.0f;
    for (int i = tid; i < DIMN; i += 256) {
        float a = qrow[i]; sq = fmaf(a, a, sq);
        float b = krow[i]; sk = fmaf(b, b, sk);
    }
#pragma unroll
    for (int off = 16; off; off >>= 1) {
        sq += __shfl_xor_sync(0xffffffffu, sq, off);
        sk += __shfl_xor_sync(0xffffffffu, sk, off);
    }
    __shared__ float redq[8], redk[8];
    __shared__ float bq, bk;
    const int warp = tid >> 5, lane = tid & 31;
    if (lane == 0) { redq[warp] = sq; redk[warp] = sk; }
    __syncthreads();
    if (tid == 0) {
        float a = 0.0f, b = 0.0f;
#pragma unroll
        for (int w = 0; w < 8; ++w) { a += redq[w]; b += redk[w]; }
        bq = a; bk = b;
    }
    __syncthreads();
    const float rq = rsqrtf(bq * (1.0f / DIMN) + EPSV);
    const float rk = rsqrtf(bk * (1.0f / DIMN) + EPSV);

    // rotary, per head pair; freqs indexed [l, d]
    for (int p = tid; p < DIMN / 2; p += 256) {
        const int head = p >> 6;           // 64 pairs per head
        const int i2   = (p & 63) * 2;     // even index within head
        const int ce   = head * HDIM + i2;
        const int co   = ce + 1;
        const float ccos = fcos[l * HDIM + i2];
        const float csin = fsin[l * HDIM + i2 + 1];

        float xe = qrow[ce] * rq * gq[ce];
        float xo = qrow[co] * rq * gq[co];
        qrow[ce] = xe * ccos - xo * csin;
        qrow[co] = xe * csin + xo * ccos;

        xe = krow[ce] * rk * gk[ce];
        xo = krow[co] * rk * gk[co];
        krow[ce] = xe * ccos - xo * csin;
        krow[co] = xe * csin + xo * ccos;
    }
}

// ---------------------------------------------------------------------------
// Flash attention, fp32, Br=Bc=32, D=128. Grid (SEQ/32, B*H), 256 threads.
// q/k/v live in g_qkv at column offsets 0 / 5120 / 10240, head offset h*128.
// Output: g_attn[(b*SEQ + q) * DIMN + h*128 + d]
// ---------------------------------------------------------------------------
#define BR 32
#define BC 32
__global__ __launch_bounds__(256) void flash_attn(
    const float* __restrict__ qkv, float* __restrict__ outp)
{
    __shared__ float Qs[BR][132];
    __shared__ float KVs[BC][132];
    __shared__ float Ps[BR][36];

    const int qb  = blockIdx.x;            // query block
    const int bh  = blockIdx.y;
    const int b   = bh / NHEADS;
    const int h   = bh % NHEADS;
    const int tid = threadIdx.x;
    const int tr  = tid >> 4;              // 0..15 -> 2 rows (tr*2+i)
    const int tc  = tid & 15;              // 0..15 -> S cols (tc*2+j), O cols (tc*8)

    const size_t rs = QKV_COLS;
    const float* qbase = qkv + (size_t)(b * SEQ + qb * BR) * rs + h * HDIM;

    // load Q tile, fold in softmax scale
    for (int i = tid; i < BR * (HDIM / 4); i += 256) {
        const int r = i >> 5, c4 = (i & 31) * 4;
        float4 v = *(const float4*)(qbase + (size_t)r * rs + c4);
        Qs[r][c4]     = v.x * SCALEV;
        Qs[r][c4 + 1] = v.y * SCALEV;
        Qs[r][c4 + 2] = v.z * SCALEV;
        Qs[r][c4 + 3] = v.w * SCALEV;
    }

    float m_i[2] = {-INFINITY, -INFINITY};
    float l_i[2] = {0.0f, 0.0f};
    float o[2][8];
#pragma unroll
    for (int i = 0; i < 2; ++i)
#pragma unroll
        for (int c = 0; c < 8; ++c) o[i][c] = 0.0f;

    for (int kb = 0; kb < SEQ / BC; ++kb) {
        const float* kbase = qkv + (size_t)(b * SEQ + kb * BC) * rs + DIMN + h * HDIM;
        __syncthreads();   // previous iteration done with KVs
        for (int i = tid; i < BC * (HDIM / 4); i += 256) {
            const int r = i >> 5, c4 = (i & 31) * 4;
            *(float4*)&KVs[r][c4] = *(const float4*)(kbase + (size_t)r * rs + c4);
        }
        __syncthreads();

        // S = Q K^T (2x2 per thread)
        float s[2][2] = {{0, 0}, {0, 0}};
#pragma unroll 8
        for (int k = 0; k < HDIM; k += 4) {
            float4 q0 = *(const float4*)&Qs[tr * 2][k];
            float4 q1 = *(const float4*)&Qs[tr * 2 + 1][k];
            float4 k0 = *(const float4*)&KVs[tc * 2][k];
            float4 k1 = *(const float4*)&KVs[tc * 2 + 1][k];
            s[0][0] += q0.x * k0.x + q0.y * k0.y + q0.z * k0.z + q0.w * k0.w;
            s[0][1] += q0.x * k1.x + q0.y * k1.y + q0.z * k1.z + q0.w * k1.w;
            s[1][0] += q1.x * k0.x + q1.y * k0.y + q1.z * k0.z + q1.w * k0.w;
            s[1][1] += q1.x * k1.x + q1.y * k1.y + q1.z * k1.z + q1.w * k1.w;
        }

        // online softmax (rows replicated across the 16 tc lanes, contiguous in warp)
#pragma unroll
        for (int i = 0; i < 2; ++i) {
            float rm = fmaxf(s[i][0], s[i][1]);
#pragma unroll
            for (int off = 8; off; off >>= 1)
                rm = fmaxf(rm, __shfl_xor_sync(0xffffffffu, rm, off));
            const float nm = fmaxf(m_i[i], rm);
            const float al = __expf(m_i[i] - nm);
            m_i[i] = nm;
            const float p0 = __expf(s[i][0] - nm);
            const float p1 = __expf(s[i][1] - nm);
            Ps[tr * 2 + i][tc * 2]     = p0;
            Ps[tr * 2 + i][tc * 2 + 1] = p1;
            float rsum = p0 + p1;
#pragma unroll
            for (int off = 8; off; off >>= 1)
                rsum += __shfl_xor_sync(0xffffffffu, rsum, off);
            l_i[i] = l_i[i] * al + rsum;
#pragma unroll
            for (int c = 0; c < 8; ++c) o[i][c] *= al;
        }
        __syncthreads();   // P written, done reading K

        // load V into KVs
        const float* vbase = qkv + (size_t)(b * SEQ + kb * BC) * rs + 2 * DIMN + h * HDIM;
        for (int i = tid; i < BC * (HDIM / 4); i += 256) {
            const int r = i >> 5, c4 = (i & 31) * 4;
            *(float4*)&KVs[r][c4] = *(const float4*)(vbase + (size_t)r * rs + c4);
        }
        __syncthreads();

        // O += P V
#pragma unroll 4
        for (int j = 0; j < BC; ++j) {
            float4 v0 = *(const float4*)&KVs[j][tc * 8];
            float4 v1 = *(const float4*)&KVs[j][tc * 8 + 4];
            const float p0 = Ps[tr * 2][j];
            const float p1 = Ps[tr * 2 + 1][j];
            o[0][0] = fmaf(p0, v0.x, o[0][0]); o[0][1] = fmaf(p0, v0.y, o[0][1]);
            o[0][2] = fmaf(p0, v0.z, o[0][2]); o[0][3] = fmaf(p0, v0.w, o[0][3]);
            o[0][4] = fmaf(p0, v1.x, o[0][4]); o[0][5] = fmaf(p0, v1.y, o[0][5]);
            o[0][6] = fmaf(p0, v1.z, o[0][6]); o[0][7] = fmaf(p0, v1.w, o[0][7]);
            o[1][0] = fmaf(p1, v0.x, o[1][0]); o[1][1] = fmaf(p1, v0.y, o[1][1]);
            o[1][2] = fmaf(p1, v0.z, o[1][2]); o[1][3] = fmaf(p1, v0.w, o[1][3]);
            o[1][4] = fmaf(p1, v1.x, o[1][4]); o[1][5] = fmaf(p1, v1.y, o[1][5]);
            o[1][6] = fmaf(p1, v1.z, o[1][6]); o[1][7] = fmaf(p1, v1.w, o[1][7]);
        }
    }

    // epilogue
#pragma unroll
    for (int i = 0; i < 2; ++i) {
        const float inv = 1.0f / l_i[i];
        const int row = b * SEQ + qb * BR + tr * 2 + i;
        float* dst = outp + (size_t)row * DIMN + h * HDIM + tc * 8;
        float4 v0, v1;
        v0.x = o[i][0] * inv; v0.y = o[i][1] * inv;
        v0.z = o[i][2] * inv; v0.w = o[i][3] * inv;
        v1.x = o[i][4] * inv; v1.y = o[i][5] * inv;
        v1.z = o[i][6] * inv; v1.w = o[i][7] * inv;
        *(float4*)(dst)     = v0;
        *(float4*)(dst + 4) = v1;
    }
}

// ---------------------------------------------------------------------------
extern "C" void kernel_launch(void* const* d_in, const int* in_sizes, int n_in,
                              void* d_out, int out_size)
{
    const float* X    = (const float*)d_in[0];
    const float* fcos = (const float*)d_in[1];
    const float* fsin = (const float*)d_in[2];
    const float* Wqkv = (const float*)d_in[3];
    const float* bqkv = (const float*)d_in[4];
    const float* gq   = (const float*)d_in[5];
    const float* gk   = (const float*)d_in[6];
    const float* Wout = (const float*)d_in[7];
    const float* bout = (const float*)d_in[8];
    float* out = (float*)d_out;

    float *qkvbuf, *attnbuf;
    cudaGetSymbolAddress((void**)&qkvbuf, g_qkv);
    cudaGetSymbolAddress((void**)&attnbuf, g_attn);

    // 1) qkv = X @ W_qkv + b_qkv
    sgemm_bias<<<dim3(QKV_COLS / 128, TOKENS / 128), 256>>>(
        X, Wqkv, bqkv, qkvbuf, TOKENS, QKV_COLS, DIMN);

    // 2) RMSNorm + RoPE in place on q,k
    rms_rope<<<TOKENS, 256>>>(qkvbuf, gq, gk, fcos, fsin);

    // 3) flash attention -> attnbuf
    flash_attn<<<dim3(SEQ / BR, BATCH * NHEADS), 256>>>(qkvbuf, attnbuf);

    // 4) out = attn @ W_out + b_out
    sgemm_bias<<<dim3(DIMN / 128, TOKENS / 128), 256>>>(
        attnbuf, Wout, bout, out, TOKENS, DIMN, DIMN);
}

// round 3
// speedup vs baseline: 1.7989x; 1.7989x over previous
#include <cuda_runtime.h>
#include <cuda_bf16.h>
#include <math.h>
#include <stdint.h>

// Problem constants
#define DIMN     5120
#define NHEADS   40
#define HDIM     128
#define BATCH    2
#define SEQ      1024
#define TOKENS   (BATCH * SEQ)        // 2048
#define QKV_COLS (3 * DIMN)           // 15360
#define EPSV     1e-6f
#define SCALEV   0.08838834764831845f // 128^-0.5

// GEMM tiling
#define GBM 128
#define GBN 128
#define GBK 32
#define GSTAGES 3
#define AROW 40                               // GBK + 8 pad (bf16 elems)
#define PLANE_BYTES (GBM * AROW * 2)          // 10240
#define STAGE_B (4 * PLANE_BYTES)             // 40960
#define GSMEM (GSTAGES * STAGE_B)             // 122880
#define NCHUNK (DIMN / GBK)                   // 160

// Scratch (no allocations allowed)
__device__ float          g_qkv[(size_t)TOKENS * QKV_COLS];     // fp32 qkv
__device__ __nv_bfloat16  g_xhi[(size_t)TOKENS * DIMN];
__device__ __nv_bfloat16  g_xlo[(size_t)TOKENS * DIMN];
__device__ __nv_bfloat16  g_ahi[(size_t)TOKENS * DIMN];         // attn out hi
__device__ __nv_bfloat16  g_alo[(size_t)TOKENS * DIMN];         // attn out lo
__device__ __nv_bfloat16  g_wqhi[(size_t)QKV_COLS * DIMN];      // W_qkv^T hi [N,K]
__device__ __nv_bfloat16  g_wqlo[(size_t)QKV_COLS * DIMN];
__device__ __nv_bfloat16  g_wohi[(size_t)DIMN * DIMN];          // W_out^T hi [N,K]
__device__ __nv_bfloat16  g_wolo[(size_t)DIMN * DIMN];

// ---------------------------------------------------------------------------
// helpers
// ---------------------------------------------------------------------------
__device__ __forceinline__ uint32_t smem_u32(const void* p) {
    uint32_t a;
    asm("{ .reg .u64 t; cvta.to.shared.u64 t, %1; cvt.u32.u64 %0, t; }" : "=r"(a) : "l"(p));
    return a;
}
__device__ __forceinline__ void cp16(uint32_t s, const void* g) {
    asm volatile("cp.async.cg.shared.global [%0], [%1], 16;" :: "r"(s), "l"(g));
}
__device__ __forceinline__ void cp_commit() {
    asm volatile("cp.async.commit_group;" ::: "memory");
}
__device__ __forceinline__ void cp_wait1() {
    asm volatile("cp.async.wait_group 1;" ::: "memory");
}
__device__ __forceinline__ void mma_bf16(float* c, const uint32_t* a, const uint32_t* b) {
    asm volatile("mma.sync.aligned.m16n8k16.row.col.f32.bf16.bf16.f32 "
        "{%0,%1,%2,%3}, {%4,%5,%6,%7}, {%8,%9}, {%0,%1,%2,%3};"
        : "+f"(c[0]), "+f"(c[1]), "+f"(c[2]), "+f"(c[3])
        : "r"(a[0]), "r"(a[1]), "r"(a[2]), "r"(a[3]), "r"(b[0]), "r"(b[1]));
}

// ---------------------------------------------------------------------------
// GEMM: C[M, Ntot] = A @ B^T + bias.  A hi/lo: [M,K] bf16, B hi/lo: [Ntot,K] bf16.
// Split product: hi*hi + hi*lo + lo*hi (fp32 accum).  K = DIMN = 5120.
// grid (M/128, Ntot/128), 256 threads.
// ---------------------------------------------------------------------------
__global__ __launch_bounds__(256) void gemm_bf16x3(
    const __nv_bfloat16* __restrict__ Ahi, const __nv_bfloat16* __restrict__ Alo,
    const __nv_bfloat16* __restrict__ Bhi, const __nv_bfloat16* __restrict__ Blo,
    const float* __restrict__ bias, float* __restrict__ C, int Ntot)
{
    extern __shared__ char gsm[];
    const uint32_t sbase = smem_u32(gsm);
    const int tid = threadIdx.x;
    const int m0  = blockIdx.x * GBM;
    const int n0  = blockIdx.y * GBN;
    const int K   = DIMN;

    const int wid  = tid >> 5, lane = tid & 31;
    const int wm   = wid & 1;        // 2 groups of 64 rows
    const int wn   = wid >> 1;       // 4 groups of 32 cols
    const int gid  = lane >> 2;      // 0..7
    const int tig  = lane & 3;       // 0..3

    // load-index precompute: 512 chunks per plane, 2 per thread
    const int r0 = tid >> 1;                 // unused pattern below uses idx math
    (void)r0;

    float acc[4][4][4];
#pragma unroll
    for (int a = 0; a < 4; ++a)
#pragma unroll
        for (int b = 0; b < 4; ++b)
#pragma unroll
            for (int c = 0; c < 4; ++c) acc[a][b][c] = 0.0f;

    // ---- stage load ----
    auto issue = [&](int s, int k0) {
        const uint32_t st = sbase + s * STAGE_B;
#pragma unroll
        for (int i = 0; i < 2; ++i) {
            const int idx = tid + 256 * i;      // 0..511
            const int row = idx >> 2;
            const int ch  = idx & 3;
            const uint32_t so = (uint32_t)(row * (AROW * 2) + ch * 16);
            const size_t ga = (size_t)(m0 + row) * K + k0 + ch * 8;
            const size_t gb = (size_t)(n0 + row) * K + k0 + ch * 8;
            cp16(st + so,                   Ahi + ga);
            cp16(st + PLANE_BYTES + so,     Alo + ga);
            cp16(st + 2 * PLANE_BYTES + so, Bhi + gb);
            cp16(st + 3 * PLANE_BYTES + so, Blo + gb);
        }
        cp_commit();
    };

    issue(0, 0);
    issue(1, GBK);

    for (int it = 0; it < NCHUNK; ++it) {
        cp_wait1();
        __syncthreads();
        const int nxt = it + 2;
        if (nxt < NCHUNK) issue(nxt % GSTAGES, nxt * GBK);

        const char* st = gsm + (it % GSTAGES) * STAGE_B;
#pragma unroll
        for (int ks = 0; ks < 2; ++ks) {
            const int cofs = (ks * 16 + tig * 2) * 2;  // byte offset along k
            uint32_t ah[4][4], al[4][4];
#pragma unroll
            for (int mt = 0; mt < 4; ++mt) {
                const int r = wm * 64 + mt * 16 + gid;
                const char* p = st + r * (AROW * 2) + cofs;
                ah[mt][0] = *(const uint32_t*)(p);
                ah[mt][1] = *(const uint32_t*)(p + 8 * AROW * 2);
                ah[mt][2] = *(const uint32_t*)(p + 16);
                ah[mt][3] = *(const uint32_t*)(p + 8 * AROW * 2 + 16);
                const char* q = p + PLANE_BYTES;
                al[mt][0] = *(const uint32_t*)(q);
                al[mt][1] = *(const uint32_t*)(q + 8 * AROW * 2);
                al[mt][2] = *(const uint32_t*)(q + 16);
                al[mt][3] = *(const uint32_t*)(q + 8 * AROW * 2 + 16);
            }
            uint32_t bh[4][2], bl[4][2];
#pragma unroll
            for (int nt = 0; nt < 4; ++nt) {
                const int r = wn * 32 + nt * 8 + gid;
                const char* p = st + 2 * PLANE_BYTES + r * (AROW * 2) + cofs;
                bh[nt][0] = *(const uint32_t*)(p);
                bh[nt][1] = *(const uint32_t*)(p + 16);
                const char* q = p + PLANE_BYTES;
                bl[nt][0] = *(const uint32_t*)(q);
                bl[nt][1] = *(const uint32_t*)(q + 16);
            }
#pragma unroll
            for (int mt = 0; mt < 4; ++mt)
#pragma unroll
                for (int nt = 0; nt < 4; ++nt) {
                    mma_bf16(acc[mt][nt], ah[mt], bh[nt]);
                    mma_bf16(acc[mt][nt], ah[mt], bl[nt]);
                    mma_bf16(acc[mt][nt], al[mt], bh[nt]);
                }
        }
        __syncthreads();
    }

    // epilogue
#pragma unroll
    for (int mt = 0; mt < 4; ++mt) {
#pragma unroll
        for (int nt = 0; nt < 4; ++nt) {
            const int row = m0 + wm * 64 + mt * 16 + gid;
            const int col = n0 + wn * 32 + nt * 8 + tig * 2;
            const float b0 = bias[col], b1 = bias[col + 1];
            float2 v0 = {acc[mt][nt][0] + b0, acc[mt][nt][1] + b1};
            float2 v1 = {acc[mt][nt][2] + b0, acc[mt][nt][3] + b1};
            *(float2*)(C + (size_t)row * Ntot + col)       = v0;
            *(float2*)(C + (size_t)(row + 8) * Ntot + col) = v1;
        }
    }
}

// ---------------------------------------------------------------------------
// elementwise split fp32 -> bf16 hi/lo
// ---------------------------------------------------------------------------
__global__ __launch_bounds__(256) void split_bf16(
    const float4* __restrict__ in, uint2* __restrict__ hi, uint2* __restrict__ lo, int n4)
{
    const int i = blockIdx.x * 256 + threadIdx.x;
    if (i >= n4) return;
    float4 v = in[i];
    __nv_bfloat16 h[4], l[4];
    float f[4] = {v.x, v.y, v.z, v.w};
#pragma unroll
    for (int j = 0; j < 4; ++j) {
        h[j] = __float2bfloat16_rn(f[j]);
        l[j] = __float2bfloat16_rn(f[j] - __bfloat162float(h[j]));
    }
    uint2 H, L;
    H.x = ((uint32_t)__bfloat16_as_ushort(h[1]) << 16) | __bfloat16_as_ushort(h[0]);
    H.y = ((uint32_t)__bfloat16_as_ushort(h[3]) << 16) | __bfloat16_as_ushort(h[2]);
    L.x = ((uint32_t)__bfloat16_as_ushort(l[1]) << 16) | __bfloat16_as_ushort(l[0]);
    L.y = ((uint32_t)__bfloat16_as_ushort(l[3]) << 16) | __bfloat16_as_ushort(l[2]);
    hi[i] = H;
    lo[i] = L;
}

// ---------------------------------------------------------------------------
// transpose + split: W [K,N] fp32 -> Whi/Wlo [N,K] bf16
// ---------------------------------------------------------------------------
__global__ __launch_bounds__(256) void transpose_split(
    const float* __restrict__ W,
    __nv_bfloat16* __restrict__ Whi, __nv_bfloat16* __restrict__ Wlo, int K, int N)
{
    __shared__ float t[32][33];
    const int n0 = blockIdx.x * 32, k0 = blockIdx.y * 32;
    const int tx = threadIdx.x, ty = threadIdx.y;
#pragma unroll
    for (int i = 0; i < 32; i += 8)
        t[ty + i][tx] = W[(size_t)(k0 + ty + i) * N + n0 + tx];
    __syncthreads();
#pragma unroll
    for (int i = 0; i < 32; i += 8) {
        float x = t[tx][ty + i];
        __nv_bfloat16 h = __float2bfloat16_rn(x);
        __nv_bfloat16 l = __float2bfloat16_rn(x - __bfloat162float(h));
        const size_t idx = (size_t)(n0 + ty + i) * K + k0 + tx;
        Whi[idx] = h;
        Wlo[idx] = l;
    }
}

// ---------------------------------------------------------------------------
// Fused RMSNorm + rotary, in place on q,k of g_qkv. One block per token.
// ---------------------------------------------------------------------------
__global__ __launch_bounds__(256) void rms_rope(
    float* __restrict__ qkv,
    const float* __restrict__ gq, const float* __restrict__ gk,
    const float* __restrict__ fcos, const float* __restrict__ fsin)
{
    const int t   = blockIdx.x;
    const int l   = t & (SEQ - 1);
    const int tid = threadIdx.x;

    float* qrow = qkv + (size_t)t * QKV_COLS;
    float* krow = qrow + DIMN;

    float sq = 0.0f, sk = 0.0f;
    for (int i = tid; i < DIMN; i += 256) {
        float a = qrow[i]; sq = fmaf(a, a, sq);
        float b = krow[i]; sk = fmaf(b, b, sk);
    }
#pragma unroll
    for (int off = 16; off; off >>= 1) {
        sq += __shfl_xor_sync(0xffffffffu, sq, off);
        sk += __shfl_xor_sync(0xffffffffu, sk, off);
    }
    __shared__ float redq[8], redk[8];
    __shared__ float bq, bk;
    const int warp = tid >> 5, lane = tid & 31;
    if (lane == 0) { redq[warp] = sq; redk[warp] = sk; }
    __syncthreads();
    if (tid == 0) {
        float a = 0.0f, b = 0.0f;
#pragma unroll
        for (int w = 0; w < 8; ++w) { a += redq[w]; b += redk[w]; }
        bq = a; bk = b;
    }
    __syncthreads();
    const float rq = rsqrtf(bq * (1.0f / DIMN) + EPSV);
    const float rk = rsqrtf(bk * (1.0f / DIMN) + EPSV);

    for (int p = tid; p < DIMN / 2; p += 256) {
        const int head = p >> 6;
        const int i2   = (p & 63) * 2;
        const int ce   = head * HDIM + i2;
        const int co   = ce + 1;
        const float ccos = fcos[l * HDIM + i2];
        const float csin = fsin[l * HDIM + i2 + 1];

        float xe = qrow[ce] * rq * gq[ce];
        float xo = qrow[co] * rq * gq[co];
        qrow[ce] = xe * ccos - xo * csin;
        qrow[co] = xe * csin + xo * ccos;

        xe = krow[ce] * rk * gk[ce];
        xo = krow[co] * rk * gk[co];
        krow[ce] = xe * ccos - xo * csin;
        krow[co] = xe * csin + xo * ccos;
    }
}

// ---------------------------------------------------------------------------
// Flash attention, fp32, Br=Bc=32, D=128. Epilogue emits bf16 hi/lo planes.
// ---------------------------------------------------------------------------
#define BR 32
#define BC 32
__global__ __launch_bounds__(256) void flash_attn(
    const float* __restrict__ qkv,
    __nv_bfloat16* __restrict__ ohi, __nv_bfloat16* __restrict__ olo)
{
    __shared__ float Qs[BR][132];
    __shared__ float KVs[BC][132];
    __shared__ float Ps[BR][36];

    const int qb  = blockIdx.x;
    const int bh  = blockIdx.y;
    const int b   = bh / NHEADS;
    const int h   = bh % NHEADS;
    const int tid = threadIdx.x;
    const int tr  = tid >> 4;
    const int tc  = tid & 15;

    const size_t rs = QKV_COLS;
    const float* qbase = qkv + (size_t)(b * SEQ + qb * BR) * rs + h * HDIM;

    for (int i = tid; i < BR * (HDIM / 4); i += 256) {
        const int r = i >> 5, c4 = (i & 31) * 4;
        float4 v = *(const float4*)(qbase + (size_t)r * rs + c4);
        Qs[r][c4]     = v.x * SCALEV;
        Qs[r][c4 + 1] = v.y * SCALEV;
        Qs[r][c4 + 2] = v.z * SCALEV;
        Qs[r][c4 + 3] = v.w * SCALEV;
    }

    float m_i[2] = {-INFINITY, -INFINITY};
    float l_i[2] = {0.0f, 0.0f};
    float o[2][8];
#pragma unroll
    for (int i = 0; i < 2; ++i)
#pragma unroll
        for (int c = 0; c < 8; ++c) o[i][c] = 0.0f;

    for (int kb = 0; kb < SEQ / BC; ++kb) {
        const float* kbase = qkv + (size_t)(b * SEQ + kb * BC) * rs + DIMN + h * HDIM;
        __syncthreads();
        for (int i = tid; i < BC * (HDIM / 4); i += 256) {
            const int r = i >> 5, c4 = (i & 31) * 4;
            *(float4*)&KVs[r][c4] = *(const float4*)(kbase + (size_t)r * rs + c4);
        }
        __syncthreads();

        float s[2][2] = {{0, 0}, {0, 0}};
#pragma unroll 8
        for (int k = 0; k < HDIM; k += 4) {
            float4 q0 = *(const float4*)&Qs[tr * 2][k];
            float4 q1 = *(const float4*)&Qs[tr * 2 + 1][k];
            float4 k0 = *(const float4*)&KVs[tc * 2][k];
            float4 k1 = *(const float4*)&KVs[tc * 2 + 1][k];
            s[0][0] += q0.x * k0.x + q0.y * k0.y + q0.z * k0.z + q0.w * k0.w;
            s[0][1] += q0.x * k1.x + q0.y * k1.y + q0.z * k1.z + q0.w * k1.w;
            s[1][0] += q1.x * k0.x + q1.y * k0.y + q1.z * k0.z + q1.w * k0.w;
            s[1][1] += q1.x * k1.x + q1.y * k1.y + q1.z * k1.z + q1.w * k1.w;
        }

#pragma unroll
        for (int i = 0; i < 2; ++i) {
            float rm = fmaxf(s[i][0], s[i][1]);
#pragma unroll
            for (int off = 8; off; off >>= 1)
                rm = fmaxf(rm, __shfl_xor_sync(0xffffffffu, rm, off));
            const float nm = fmaxf(m_i[i], rm);
            const float al = __expf(m_i[i] - nm);
            m_i[i] = nm;
            const float p0 = __expf(s[i][0] - nm);
            const float p1 = __expf(s[i][1] - nm);
            Ps[tr * 2 + i][tc * 2]     = p0;
            Ps[tr * 2 + i][tc * 2 + 1] = p1;
            float rsum = p0 + p1;
#pragma unroll
            for (int off = 8; off; off >>= 1)
                rsum += __shfl_xor_sync(0xffffffffu, rsum, off);
            l_i[i] = l_i[i] * al + rsum;
#pragma unroll
            for (int c = 0; c < 8; ++c) o[i][c] *= al;
        }
        __syncthreads();

        const float* vbase = qkv + (size_t)(b * SEQ + kb * BC) * rs + 2 * DIMN + h * HDIM;
        for (int i = tid; i < BC * (HDIM / 4); i += 256) {
            const int r = i >> 5, c4 = (i & 31) * 4;
            *(float4*)&KVs[r][c4] = *(const float4*)(vbase + (size_t)r * rs + c4);
        }
        __syncthreads();

#pragma unroll 4
        for (int j = 0; j < BC; ++j) {
            float4 v0 = *(const float4*)&KVs[j][tc * 8];
            float4 v1 = *(const float4*)&KVs[j][tc * 8 + 4];
            const float p0 = Ps[tr * 2][j];
            const float p1 = Ps[tr * 2 + 1][j];
            o[0][0] = fmaf(p0, v0.x, o[0][0]); o[0][1] = fmaf(p0, v0.y, o[0][1]);
            o[0][2] = fmaf(p0, v0.z, o[0][2]); o[0][3] = fmaf(p0, v0.w, o[0][3]);
            o[0][4] = fmaf(p0, v1.x, o[0][4]); o[0][5] = fmaf(p0, v1.y, o[0][5]);
            o[0][6] = fmaf(p0, v1.z, o[0][6]); o[0][7] = fmaf(p0, v1.w, o[0][7]);
            o[1][0] = fmaf(p1, v0.x, o[1][0]); o[1][1] = fmaf(p1, v0.y, o[1][1]);
            o[1][2] = fmaf(p1, v0.z, o[1][2]); o[1][3] = fmaf(p1, v0.w, o[1][3]);
            o[1][4] = fmaf(p1, v1.x, o[1][4]); o[1][5] = fmaf(p1, v1.y, o[1][5]);
            o[1][6] = fmaf(p1, v1.z, o[1][6]); o[1][7] = fmaf(p1, v1.w, o[1][7]);
        }
    }

#pragma unroll
    for (int i = 0; i < 2; ++i) {
        const float inv = 1.0f / l_i[i];
        const int row = b * SEQ + qb * BR + tr * 2 + i;
        const size_t base = (size_t)row * DIMN + h * HDIM + tc * 8;
        uint32_t H[4], L[4];
#pragma unroll
        for (int c4 = 0; c4 < 4; ++c4) {
            float f0 = o[i][c4 * 2] * inv;
            float f1 = o[i][c4 * 2 + 1] * inv;
            __nv_bfloat16 h0 = __float2bfloat16_rn(f0);
            __nv_bfloat16 h1 = __float2bfloat16_rn(f1);
            __nv_bfloat16 l0 = __float2bfloat16_rn(f0 - __bfloat162float(h0));
            __nv_bfloat16 l1 = __float2bfloat16_rn(f1 - __bfloat162float(h1));
            H[c4] = ((uint32_t)__bfloat16_as_ushort(h1) << 16) | __bfloat16_as_ushort(h0);
            L[c4] = ((uint32_t)__bfloat16_as_ushort(l1) << 16) | __bfloat16_as_ushort(l0);
        }
        *(uint4*)(ohi + base) = *(uint4*)H;
        *(uint4*)(olo + base) = *(uint4*)L;
    }
}

// ---------------------------------------------------------------------------
extern "C" void kernel_launch(void* const* d_in, const int* in_sizes, int n_in,
                              void* d_out, int out_size)
{
    const float* X    = (const float*)d_in[0];
    const float* fcos = (const float*)d_in[1];
    const float* fsin = (const float*)d_in[2];
    const float* Wqkv = (const float*)d_in[3];
    const float* bqkv = (const float*)d_in[4];
    const float* gq   = (const float*)d_in[5];
    const float* gk   = (const float*)d_in[6];
    const float* Wout = (const float*)d_in[7];
    const float* bout = (const float*)d_in[8];
    float* out = (float*)d_out;

    float *qkvbuf;
    __nv_bfloat16 *xhi, *xlo, *ahi, *alo, *wqhi, *wqlo, *wohi, *wolo;
    cudaGetSymbolAddress((void**)&qkvbuf, g_qkv);
    cudaGetSymbolAddress((void**)&xhi, g_xhi);
    cudaGetSymbolAddress((void**)&xlo, g_xlo);
    cudaGetSymbolAddress((void**)&ahi, g_ahi);
    cudaGetSymbolAddress((void**)&alo, g_alo);
    cudaGetSymbolAddress((void**)&wqhi, g_wqhi);
    cudaGetSymbolAddress((void**)&wqlo, g_wqlo);
    cudaGetSymbolAddress((void**)&wohi, g_wohi);
    cudaGetSymbolAddress((void**)&wolo, g_wolo);

    cudaFuncSetAttribute(gemm_bf16x3, cudaFuncAttributeMaxDynamicSharedMemorySize, GSMEM);

    // 0) precision-split operands
    split_bf16<<<(TOKENS * DIMN / 4 + 255) / 256, 256>>>(
        (const float4*)X, (uint2*)xhi, (uint2*)xlo, TOKENS * DIMN / 4);
    transpose_split<<<dim3(QKV_COLS / 32, DIMN / 32), dim3(32, 8)>>>(
        Wqkv, wqhi, wqlo, DIMN, QKV_COLS);
    transpose_split<<<dim3(DIMN / 32, DIMN / 32), dim3(32, 8)>>>(
        Wout, wohi, wolo, DIMN, DIMN);

    // 1) qkv = X @ W_qkv + b_qkv  (bf16x3 tensor-core GEMM)
    gemm_bf16x3<<<dim3(TOKENS / GBM, QKV_COLS / GBN), 256, GSMEM>>>(
        xhi, xlo, wqhi, wqlo, bqkv, qkvbuf, QKV_COLS);

    // 2) RMSNorm + RoPE in place
    rms_rope<<<TOKENS, 256>>>(qkvbuf, gq, gk, fcos, fsin);

    // 3) flash attention -> bf16 hi/lo planes
    flash_attn<<<dim3(SEQ / BR, BATCH * NHEADS), 256>>>(qkvbuf, ahi, alo);

    // 4) out = attn @ W_out + b_out
    gemm_bf16x3<<<dim3(TOKENS / GBM, DIMN / GBN), 256, GSMEM>>>(
        ahi, alo, wohi, wolo, bout, out, DIMN);
}

// round 4
// speedup vs baseline: 1.8220x; 1.0128x over previous
#include <cuda_runtime.h>
#include <cuda_bf16.h>
#include <math.h>
#include <stdint.h>

// Problem constants
#define DIMN     5120
#define NHEADS   40
#define HDIM     128
#define BATCH    2
#define SEQ      1024
#define TOKENS   (BATCH * SEQ)        // 2048
#define QKV_COLS (3 * DIMN)           // 15360
#define EPSV     1e-6f
#define SCALEV   0.08838834764831845f // 128^-0.5

// GEMM tiling: CTA 128x256, 8 warps of 64x64, BK=32, 3 stages
#define GBM 128
#define GBN 256
#define GBK 32
#define GSTAGES 3
#define AROWB 80                              // (32+8) bf16 * 2B per row
#define A_PLANE (GBM * AROWB)                 // 10240
#define B_PLANE (GBN * AROWB)                 // 20480
#define STAGE_B (2 * A_PLANE + 2 * B_PLANE)   // 61440
#define GSMEM (GSTAGES * STAGE_B)             // 184320
#define NCHUNK (DIMN / GBK)                   // 160

// Scratch (no allocations allowed)
__device__ float          g_qkv[(size_t)TOKENS * QKV_COLS];
__device__ __nv_bfloat16  g_xhi[(size_t)TOKENS * DIMN];
__device__ __nv_bfloat16  g_xlo[(size_t)TOKENS * DIMN];
__device__ __nv_bfloat16  g_ahi[(size_t)TOKENS * DIMN];
__device__ __nv_bfloat16  g_alo[(size_t)TOKENS * DIMN];
__device__ __nv_bfloat16  g_wqhi[(size_t)QKV_COLS * DIMN];
__device__ __nv_bfloat16  g_wqlo[(size_t)QKV_COLS * DIMN];
__device__ __nv_bfloat16  g_wohi[(size_t)DIMN * DIMN];
__device__ __nv_bfloat16  g_wolo[(size_t)DIMN * DIMN];

// ---------------------------------------------------------------------------
__device__ __forceinline__ uint32_t smem_u32(const void* p) {
    uint32_t a;
    asm("{ .reg .u64 t; cvta.to.shared.u64 t, %1; cvt.u32.u64 %0, t; }" : "=r"(a) : "l"(p));
    return a;
}
__device__ __forceinline__ void cp16(uint32_t s, const void* g) {
    asm volatile("cp.async.cg.shared.global [%0], [%1], 16;" :: "r"(s), "l"(g));
}
__device__ __forceinline__ void cp_commit() {
    asm volatile("cp.async.commit_group;" ::: "memory");
}
__device__ __forceinline__ void cp_wait1() {
    asm volatile("cp.async.wait_group 1;" ::: "memory");
}
__device__ __forceinline__ void mma_bf16(float* c, const uint32_t* a, const uint32_t* b) {
    asm volatile("mma.sync.aligned.m16n8k16.row.col.f32.bf16.bf16.f32 "
        "{%0,%1,%2,%3}, {%4,%5,%6,%7}, {%8,%9}, {%0,%1,%2,%3};"
        : "+f"(c[0]), "+f"(c[1]), "+f"(c[2]), "+f"(c[3])
        : "r"(a[0]), "r"(a[1]), "r"(a[2]), "r"(a[3]), "r"(b[0]), "r"(b[1]));
}

// ---------------------------------------------------------------------------
// GEMM: C[M, Ntot] = A @ B^T + bias, 3-pass split bf16 (hh + hl + lh).
// A hi/lo: [M,K] bf16.  B hi/lo: [Ntot,K] bf16.  K = DIMN.
// grid (M/128, Ntot/256), 256 threads, warptile 64x64.
// ---------------------------------------------------------------------------
__global__ __launch_bounds__(256, 1) void gemm_bf16x3(
    const __nv_bfloat16* __restrict__ Ahi, const __nv_bfloat16* __restrict__ Alo,
    const __nv_bfloat16* __restrict__ Bhi, const __nv_bfloat16* __restrict__ Blo,
    const float* __restrict__ bias, float* __restrict__ C, int Ntot)
{
    extern __shared__ char gsm[];
    const uint32_t sbase = smem_u32(gsm);
    const int tid = threadIdx.x;
    const int m0  = blockIdx.x * GBM;
    const int n0  = blockIdx.y * GBN;
    const int K   = DIMN;

    const int wid  = tid >> 5, lane = tid & 31;
    const int wm   = wid & 1;        // 2 groups of 64 rows
    const int wn   = wid >> 1;       // 4 groups of 64 cols
    const int gid  = lane >> 2;      // 0..7
    const int tig  = lane & 3;       // 0..3

    float acc[4][8][4];
#pragma unroll
    for (int a = 0; a < 4; ++a)
#pragma unroll
        for (int b = 0; b < 8; ++b)
#pragma unroll
            for (int c = 0; c < 4; ++c) acc[a][b][c] = 0.0f;

    auto issue = [&](int s, int k0) {
        const uint32_t st = sbase + s * STAGE_B;
        // A: 2 planes x 512 16B-chunks
#pragma unroll
        for (int i = 0; i < 4; ++i) {
            const int idx = tid + 256 * i;
            const int p   = idx >> 9;
            const int r   = (idx >> 2) & 127;
            const int ch  = idx & 3;
            const __nv_bfloat16* src = (p ? Alo : Ahi) + (size_t)(m0 + r) * K + k0 + ch * 8;
            cp16(st + p * A_PLANE + r * AROWB + ch * 16, src);
        }
        // B: 2 planes x 1024 16B-chunks
#pragma unroll
        for (int i = 0; i < 8; ++i) {
            const int idx = tid + 256 * i;
            const int p   = idx >> 10;
            const int r   = (idx >> 2) & 255;
            const int ch  = idx & 3;
            const __nv_bfloat16* src = (p ? Blo : Bhi) + (size_t)(n0 + r) * K + k0 + ch * 8;
            cp16(st + 2 * A_PLANE + p * B_PLANE + r * AROWB + ch * 16, src);
        }
        cp_commit();
    };

    issue(0, 0);
    issue(1, GBK);

    for (int it = 0; it < NCHUNK; ++it) {
        cp_wait1();
        __syncthreads();
        const int nxt = it + 2;
        if (nxt < NCHUNK) issue(nxt % GSTAGES, nxt * GBK);

        const char* st = gsm + (it % GSTAGES) * STAGE_B;
#pragma unroll
        for (int ks = 0; ks < 2; ++ks) {
            const int cofs = (ks * 16 + tig * 2) * 2;
            uint32_t ah[4][4], al[4][4];
#pragma unroll
            for (int mt = 0; mt < 4; ++mt) {
                const char* p = st + (wm * 64 + mt * 16 + gid) * AROWB + cofs;
                ah[mt][0] = *(const uint32_t*)(p);
                ah[mt][1] = *(const uint32_t*)(p + 8 * AROWB);
                ah[mt][2] = *(const uint32_t*)(p + 16);
                ah[mt][3] = *(const uint32_t*)(p + 8 * AROWB + 16);
                const char* q = p + A_PLANE;
                al[mt][0] = *(const uint32_t*)(q);
                al[mt][1] = *(const uint32_t*)(q + 8 * AROWB);
                al[mt][2] = *(const uint32_t*)(q + 16);
                al[mt][3] = *(const uint32_t*)(q + 8 * AROWB + 16);
            }
            uint32_t bh[8][2], bl[8][2];
#pragma unroll
            for (int nt = 0; nt < 8; ++nt) {
                const char* p = st + 2 * A_PLANE + (wn * 64 + nt * 8 + gid) * AROWB + cofs;
                bh[nt][0] = *(const uint32_t*)(p);
                bh[nt][1] = *(const uint32_t*)(p + 16);
                const char* q = p + B_PLANE;
                bl[nt][0] = *(const uint32_t*)(q);
                bl[nt][1] = *(const uint32_t*)(q + 16);
            }
            // pass-major ordering: consecutive MMAs hit different accumulators
#pragma unroll
            for (int mt = 0; mt < 4; ++mt)
#pragma unroll
                for (int nt = 0; nt < 8; ++nt)
                    mma_bf16(acc[mt][nt], ah[mt], bh[nt]);
#pragma unroll
            for (int mt = 0; mt < 4; ++mt)
#pragma unroll
                for (int nt = 0; nt < 8; ++nt)
                    mma_bf16(acc[mt][nt], ah[mt], bl[nt]);
#pragma unroll
            for (int mt = 0; mt < 4; ++mt)
#pragma unroll
                for (int nt = 0; nt < 8; ++nt)
                    mma_bf16(acc[mt][nt], al[mt], bh[nt]);
        }
        __syncthreads();
    }

    // epilogue
#pragma unroll
    for (int mt = 0; mt < 4; ++mt) {
#pragma unroll
        for (int nt = 0; nt < 8; ++nt) {
            const int row = m0 + wm * 64 + mt * 16 + gid;
            const int col = n0 + wn * 64 + nt * 8 + tig * 2;
            const float b0 = bias[col], b1 = bias[col + 1];
            float2 v0 = {acc[mt][nt][0] + b0, acc[mt][nt][1] + b1};
            float2 v1 = {acc[mt][nt][2] + b0, acc[mt][nt][3] + b1};
            *(float2*)(C + (size_t)row * Ntot + col)       = v0;
            *(float2*)(C + (size_t)(row + 8) * Ntot + col) = v1;
        }
    }
}

// ---------------------------------------------------------------------------
// elementwise split fp32 -> bf16 hi/lo
// ---------------------------------------------------------------------------
__global__ __launch_bounds__(256) void split_bf16(
    const float4* __restrict__ in, uint2* __restrict__ hi, uint2* __restrict__ lo, int n4)
{
    const int i = blockIdx.x * 256 + threadIdx.x;
    if (i >= n4) return;
    float4 v = in[i];
    __nv_bfloat16 h[4], l[4];
    float f[4] = {v.x, v.y, v.z, v.w};
#pragma unroll
    for (int j = 0; j < 4; ++j) {
        h[j] = __float2bfloat16_rn(f[j]);
        l[j] = __float2bfloat16_rn(f[j] - __bfloat162float(h[j]));
    }
    uint2 H, L;
    H.x = ((uint32_t)__bfloat16_as_ushort(h[1]) << 16) | __bfloat16_as_ushort(h[0]);
    H.y = ((uint32_t)__bfloat16_as_ushort(h[3]) << 16) | __bfloat16_as_ushort(h[2]);
    L.x = ((uint32_t)__bfloat16_as_ushort(l[1]) << 16) | __bfloat16_as_ushort(l[0]);
    L.y = ((uint32_t)__bfloat16_as_ushort(l[3]) << 16) | __bfloat16_as_ushort(l[2]);
    hi[i] = H;
    lo[i] = L;
}

// ---------------------------------------------------------------------------
// transpose + split: W [K,N] fp32 -> Whi/Wlo [N,K] bf16
// ---------------------------------------------------------------------------
__global__ __launch_bounds__(256) void transpose_split(
    const float* __restrict__ W,
    __nv_bfloat16* __restrict__ Whi, __nv_bfloat16* __restrict__ Wlo, int K, int N)
{
    __shared__ float t[32][33];
    const int n0 = blockIdx.x * 32, k0 = blockIdx.y * 32;
    const int tx = threadIdx.x, ty = threadIdx.y;
#pragma unroll
    for (int i = 0; i < 32; i += 8)
        t[ty + i][tx] = W[(size_t)(k0 + ty + i) * N + n0 + tx];
    __syncthreads();
#pragma unroll
    for (int i = 0; i < 32; i += 8) {
        float x = t[tx][ty + i];
        __nv_bfloat16 h = __float2bfloat16_rn(x);
        __nv_bfloat16 l = __float2bfloat16_rn(x - __bfloat162float(h));
        const size_t idx = (size_t)(n0 + ty + i) * K + k0 + tx;
        Whi[idx] = h;
        Wlo[idx] = l;
    }
}

// ---------------------------------------------------------------------------
// Fused RMSNorm + rotary, in place on q,k of g_qkv. One block per token.
// ---------------------------------------------------------------------------
__global__ __launch_bounds__(256) void rms_rope(
    float* __restrict__ qkv,
    const float* __restrict__ gq, const float* __restrict__ gk,
    const float* __restrict__ fcos, const float* __restrict__ fsin)
{
    const int t   = blockIdx.x;
    const int l   = t & (SEQ - 1);
    const int tid = threadIdx.x;

    float* qrow = qkv + (size_t)t * QKV_COLS;
    float* krow = qrow + DIMN;

    float sq = 0.0f, sk = 0.0f;
    for (int i = tid; i < DIMN; i += 256) {
        float a = qrow[i]; sq = fmaf(a, a, sq);
        float b = krow[i]; sk = fmaf(b, b, sk);
    }
#pragma unroll
    for (int off = 16; off; off >>= 1) {
        sq += __shfl_xor_sync(0xffffffffu, sq, off);
        sk += __shfl_xor_sync(0xffffffffu, sk, off);
    }
    __shared__ float redq[8], redk[8];
    __shared__ float bq, bk;
    const int warp = tid >> 5, lane = tid & 31;
    if (lane == 0) { redq[warp] = sq; redk[warp] = sk; }
    __syncthreads();
    if (tid == 0) {
        float a = 0.0f, b = 0.0f;
#pragma unroll
        for (int w = 0; w < 8; ++w) { a += redq[w]; b += redk[w]; }
        bq = a; bk = b;
    }
    __syncthreads();
    const float rq = rsqrtf(bq * (1.0f / DIMN) + EPSV);
    const float rk = rsqrtf(bk * (1.0f / DIMN) + EPSV);

    for (int p = tid; p < DIMN / 2; p += 256) {
        const int head = p >> 6;
        const int i2   = (p & 63) * 2;
        const int ce   = head * HDIM + i2;
        const int co   = ce + 1;
        const float ccos = fcos[l * HDIM + i2];
        const float csin = fsin[l * HDIM + i2 + 1];

        float xe = qrow[ce] * rq * gq[ce];
        float xo = qrow[co] * rq * gq[co];
        qrow[ce] = xe * ccos - xo * csin;
        qrow[co] = xe * csin + xo * ccos;

        xe = krow[ce] * rk * gk[ce];
        xo = krow[co] * rk * gk[co];
        krow[ce] = xe * ccos - xo * csin;
        krow[co] = xe * csin + xo * ccos;
    }
}

// ---------------------------------------------------------------------------
// Flash attention, fp32, Br=Bc=32, D=128. Epilogue emits bf16 hi/lo planes.
// ---------------------------------------------------------------------------
#define BR 32
#define BC 32
__global__ __launch_bounds__(256) void flash_attn(
    const float* __restrict__ qkv,
    __nv_bfloat16* __restrict__ ohi, __nv_bfloat16* __restrict__ olo)
{
    __shared__ float Qs[BR][132];
    __shared__ float KVs[BC][132];
    __shared__ float Ps[BR][36];

    const int qb  = blockIdx.x;
    const int bh  = blockIdx.y;
    const int b   = bh / NHEADS;
    const int h   = bh % NHEADS;
    const int tid = threadIdx.x;
    const int tr  = tid >> 4;
    const int tc  = tid & 15;

    const size_t rs = QKV_COLS;
    const float* qbase = qkv + (size_t)(b * SEQ + qb * BR) * rs + h * HDIM;

    for (int i = tid; i < BR * (HDIM / 4); i += 256) {
        const int r = i >> 5, c4 = (i & 31) * 4;
        float4 v = *(const float4*)(qbase + (size_t)r * rs + c4);
        Qs[r][c4]     = v.x * SCALEV;
        Qs[r][c4 + 1] = v.y * SCALEV;
        Qs[r][c4 + 2] = v.z * SCALEV;
        Qs[r][c4 + 3] = v.w * SCALEV;
    }

    float m_i[2] = {-INFINITY, -INFINITY};
    float l_i[2] = {0.0f, 0.0f};
    float o[2][8];
#pragma unroll
    for (int i = 0; i < 2; ++i)
#pragma unroll
        for (int c = 0; c < 8; ++c) o[i][c] = 0.0f;

    for (int kb = 0; kb < SEQ / BC; ++kb) {
        const float* kbase = qkv + (size_t)(b * SEQ + kb * BC) * rs + DIMN + h * HDIM;
        __syncthreads();
        for (int i = tid; i < BC * (HDIM / 4); i += 256) {
            const int r = i >> 5, c4 = (i & 31) * 4;
            *(float4*)&KVs[r][c4] = *(const float4*)(kbase + (size_t)r * rs + c4);
        }
        __syncthreads();

        float s[2][2] = {{0, 0}, {0, 0}};
#pragma unroll 8
        for (int k = 0; k < HDIM; k += 4) {
            float4 q0 = *(const float4*)&Qs[tr * 2][k];
            float4 q1 = *(const float4*)&Qs[tr * 2 + 1][k];
            float4 k0 = *(const float4*)&KVs[tc * 2][k];
            float4 k1 = *(const float4*)&KVs[tc * 2 + 1][k];
            s[0][0] += q0.x * k0.x + q0.y * k0.y + q0.z * k0.z + q0.w * k0.w;
            s[0][1] += q0.x * k1.x + q0.y * k1.y + q0.z * k1.z + q0.w * k1.w;
            s[1][0] += q1.x * k0.x + q1.y * k0.y + q1.z * k0.z + q1.w * k0.w;
            s[1][1] += q1.x * k1.x + q1.y * k1.y + q1.z * k1.z + q1.w * k1.w;
        }

#pragma unroll
        for (int i = 0; i < 2; ++i) {
            float rm = fmaxf(s[i][0], s[i][1]);
#pragma unroll
            for (int off = 8; off; off >>= 1)
                rm = fmaxf(rm, __shfl_xor_sync(0xffffffffu, rm, off));
            const float nm = fmaxf(m_i[i], rm);
            const float al = __expf(m_i[i] - nm);
            m_i[i] = nm;
            const float p0 = __expf(s[i][0] - nm);
            const float p1 = __expf(s[i][1] - nm);
            Ps[tr * 2 + i][tc * 2]     = p0;
            Ps[tr * 2 + i][tc * 2 + 1] = p1;
            float rsum = p0 + p1;
#pragma unroll
            for (int off = 8; off; off >>= 1)
                rsum += __shfl_xor_sync(0xffffffffu, rsum, off);
            l_i[i] = l_i[i] * al + rsum;
#pragma unroll
            for (int c = 0; c < 8; ++c) o[i][c] *= al;
        }
        __syncthreads();

        const float* vbase = qkv + (size_t)(b * SEQ + kb * BC) * rs + 2 * DIMN + h * HDIM;
        for (int i = tid; i < BC * (HDIM / 4); i += 256) {
            const int r = i >> 5, c4 = (i & 31) * 4;
            *(float4*)&KVs[r][c4] = *(const float4*)(vbase + (size_t)r * rs + c4);
        }
        __syncthreads();

#pragma unroll 4
        for (int j = 0; j < BC; ++j) {
            float4 v0 = *(const float4*)&KVs[j][tc * 8];
            float4 v1 = *(const float4*)&KVs[j][tc * 8 + 4];
            const float p0 = Ps[tr * 2][j];
            const float p1 = Ps[tr * 2 + 1][j];
            o[0][0] = fmaf(p0, v0.x, o[0][0]); o[0][1] = fmaf(p0, v0.y, o[0][1]);
            o[0][2] = fmaf(p0, v0.z, o[0][2]); o[0][3] = fmaf(p0, v0.w, o[0][3]);
            o[0][4] = fmaf(p0, v1.x, o[0][4]); o[0][5] = fmaf(p0, v1.y, o[0][5]);
            o[0][6] = fmaf(p0, v1.z, o[0][6]); o[0][7] = fmaf(p0, v1.w, o[0][7]);
            o[1][0] = fmaf(p1, v0.x, o[1][0]); o[1][1] = fmaf(p1, v0.y, o[1][1]);
            o[1][2] = fmaf(p1, v0.z, o[1][2]); o[1][3] = fmaf(p1, v0.w, o[1][3]);
            o[1][4] = fmaf(p1, v1.x, o[1][4]); o[1][5] = fmaf(p1, v1.y, o[1][5]);
            o[1][6] = fmaf(p1, v1.z, o[1][6]); o[1][7] = fmaf(p1, v1.w, o[1][7]);
        }
    }

#pragma unroll
    for (int i = 0; i < 2; ++i) {
        const float inv = 1.0f / l_i[i];
        const int row = b * SEQ + qb * BR + tr * 2 + i;
        const size_t base = (size_t)row * DIMN + h * HDIM + tc * 8;
        uint32_t H[4], L[4];
#pragma unroll
        for (int c4 = 0; c4 < 4; ++c4) {
            float f0 = o[i][c4 * 2] * inv;
            float f1 = o[i][c4 * 2 + 1] * inv;
            __nv_bfloat16 h0 = __float2bfloat16_rn(f0);
            __nv_bfloat16 h1 = __float2bfloat16_rn(f1);
            __nv_bfloat16 l0 = __float2bfloat16_rn(f0 - __bfloat162float(h0));
            __nv_bfloat16 l1 = __float2bfloat16_rn(f1 - __bfloat162float(h1));
            H[c4] = ((uint32_t)__bfloat16_as_ushort(h1) << 16) | __bfloat16_as_ushort(h0);
            L[c4] = ((uint32_t)__bfloat16_as_ushort(l1) << 16) | __bfloat16_as_ushort(l0);
        }
        *(uint4*)(ohi + base) = *(uint4*)H;
        *(uint4*)(olo + base) = *(uint4*)L;
    }
}

// ---------------------------------------------------------------------------
extern "C" void kernel_launch(void* const* d_in, const int* in_sizes, int n_in,
                              void* d_out, int out_size)
{
    const float* X    = (const float*)d_in[0];
    const float* fcos = (const float*)d_in[1];
    const float* fsin = (const float*)d_in[2];
    const float* Wqkv = (const float*)d_in[3];
    const float* bqkv = (const float*)d_in[4];
    const float* gq   = (const float*)d_in[5];
    const float* gk   = (const float*)d_in[6];
    const float* Wout = (const float*)d_in[7];
    const float* bout = (const float*)d_in[8];
    float* out = (float*)d_out;

    float *qkvbuf;
    __nv_bfloat16 *xhi, *xlo, *ahi, *alo, *wqhi, *wqlo, *wohi, *wolo;
    cudaGetSymbolAddress((void**)&qkvbuf, g_qkv);
    cudaGetSymbolAddress((void**)&xhi, g_xhi);
    cudaGetSymbolAddress((void**)&xlo, g_xlo);
    cudaGetSymbolAddress((void**)&ahi, g_ahi);
    cudaGetSymbolAddress((void**)&alo, g_alo);
    cudaGetSymbolAddress((void**)&wqhi, g_wqhi);
    cudaGetSymbolAddress((void**)&wqlo, g_wqlo);
    cudaGetSymbolAddress((void**)&wohi, g_wohi);
    cudaGetSymbolAddress((void**)&wolo, g_wolo);

    cudaFuncSetAttribute(gemm_bf16x3, cudaFuncAttributeMaxDynamicSharedMemorySize, GSMEM);

    // 0) precision-split operands
    split_bf16<<<(TOKENS * DIMN / 4 + 255) / 256, 256>>>(
        (const float4*)X, (uint2*)xhi, (uint2*)xlo, TOKENS * DIMN / 4);
    transpose_split<<<dim3(QKV_COLS / 32, DIMN / 32), dim3(32, 8)>>>(
        Wqkv, wqhi, wqlo, DIMN, QKV_COLS);
    transpose_split<<<dim3(DIMN / 32, DIMN / 32), dim3(32, 8)>>>(
        Wout, wohi, wolo, DIMN, DIMN);

    // 1) qkv = X @ W_qkv + b_qkv
    gemm_bf16x3<<<dim3(TOKENS / GBM, QKV_COLS / GBN), 256, GSMEM>>>(
        xhi, xlo, wqhi, wqlo, bqkv, qkvbuf, QKV_COLS);

    // 2) RMSNorm + RoPE in place
    rms_rope<<<TOKENS, 256>>>(qkvbuf, gq, gk, fcos, fsin);

    // 3) flash attention -> bf16 hi/lo planes
    flash_attn<<<dim3(SEQ / BR, BATCH * NHEADS), 256>>>(qkvbuf, ahi, alo);

    // 4) out = attn @ W_out + b_out
    gemm_bf16x3<<<dim3(TOKENS / GBM, DIMN / GBN), 256, GSMEM>>>(
        ahi, alo, wohi, wolo, bout, out, DIMN);
}